// round 12
// baseline (speedup 1.0000x reference)
#include <cuda_runtime.h>
#include <cuda_fp16.h>

#define BB 2
#define LL 2048
#define DM 1024
#define NH 16
#define DKV 64
#define NEGV (-10000.0f)
#define TQ 128
#define TK 64
#define NT (LL / TK)
#define L2E 1.4426950408889634f

// Scratch (device globals: allocation-free per harness rules)
__device__ __align__(16) __half g_hq[(size_t)BB * LL * DM];
__device__ __align__(16) __half g_hk[(size_t)BB * LL * DM];
__device__ __align__(16) __half g_hv[(size_t)BB * LL * DM];
__device__ __align__(16) __half g_hw[4][(size_t)DM * DM];
__device__ __align__(16) __half g_Qh[(size_t)BB * NH * LL * DKV];
__device__ __align__(16) __half g_Kh[(size_t)BB * NH * LL * DKV];
__device__ __align__(16) __half g_Vh[(size_t)BB * NH * LL * DKV];
__device__ __align__(16) __half g_BMh[(size_t)BB * LL * LL];
__device__ __align__(16) __half g_O[(size_t)BB * LL * DM];

__device__ __forceinline__ unsigned pack2(float x, float y) {
    __half2 h = __floats2half2_rn(x, y);
    return *reinterpret_cast<unsigned*>(&h);
}

__device__ __forceinline__ float ex2f(float x) {
    float y;
    asm("ex2.approx.f32 %0,%1;" : "=f"(y) : "f"(x));
    return y;
}

__device__ __forceinline__ unsigned s2u(const void* p) {
    return (unsigned)__cvta_generic_to_shared(p);
}

__device__ __forceinline__ void cpa16(void* dst, const void* src) {
    asm volatile("cp.async.cg.shared.global [%0],[%1],16;" ::"r"(s2u(dst)),
                 "l"(src));
}
#define CPCOMMIT asm volatile("cp.async.commit_group;")
#define CPWAIT(n) asm volatile("cp.async.wait_group %0;" ::"n"(n))

__device__ __forceinline__ void ldsm4(unsigned& r0, unsigned& r1, unsigned& r2,
                                      unsigned& r3, unsigned addr) {
    asm volatile("ldmatrix.sync.aligned.m8n8.x4.shared.b16 {%0,%1,%2,%3},[%4];"
                 : "=r"(r0), "=r"(r1), "=r"(r2), "=r"(r3)
                 : "r"(addr));
}

__device__ __forceinline__ void ldsm4t(unsigned& r0, unsigned& r1, unsigned& r2,
                                       unsigned& r3, unsigned addr) {
    asm volatile(
        "ldmatrix.sync.aligned.m8n8.x4.trans.shared.b16 {%0,%1,%2,%3},[%4];"
        : "=r"(r0), "=r"(r1), "=r"(r2), "=r"(r3)
        : "r"(addr));
}

__device__ __forceinline__ void mma16(float* c, unsigned a0, unsigned a1,
                                      unsigned a2, unsigned a3, unsigned b0,
                                      unsigned b1) {
    asm volatile(
        "mma.sync.aligned.m16n8k16.row.col.f32.f16.f16.f32 "
        "{%0,%1,%2,%3},{%4,%5,%6,%7},{%8,%9},{%0,%1,%2,%3};"
        : "+f"(c[0]), "+f"(c[1]), "+f"(c[2]), "+f"(c[3])
        : "r"(a0), "r"(a1), "r"(a2), "r"(a3), "r"(b0), "r"(b1));
}

// ---------------------------------------------------------------------------
// Kernel 0: merged prep. Blocks [0,4096): fp32->fp16 convert of activations
// + weights. Blocks [4096,12288): fuse mask+bias -> BM (fp16; -10000 is
// exactly representable in half so masking semantics are preserved).
// ---------------------------------------------------------------------------
struct PrepArgs {
    const float4* s[7];
    uint2* d[7];
    const int4* mask;
    const float4* bias;
    uint2* bmh;
};
__global__ __launch_bounds__(256) void prep_kernel(PrepArgs a) {
    int bid = blockIdx.x;
    if (bid < 4096) {
        int ti, base;
        if (bid < 3072) {
            ti = bid >> 10;
            base = bid & 1023;
        } else {
            ti = 3 + ((bid - 3072) >> 8);
            base = (bid - 3072) & 255;
        }
        const float4* s = a.s[ti];
        uint2* d = a.d[ti];
        size_t off = (size_t)base * 1024 + threadIdx.x;
#pragma unroll
        for (int i = 0; i < 4; i++) {
            float4 v = s[off + i * 256];
            uint2 u;
            u.x = pack2(v.x, v.y);
            u.y = pack2(v.z, v.w);
            d[off + i * 256] = u;
        }
    } else {
        size_t i = (size_t)(bid - 4096) * 256 + threadIdx.x;
        int4 m = a.mask[i];
        float4 bv = a.bias[i];
        uint2 r;
        r.x = pack2(m.x ? bv.x : NEGV, m.y ? bv.y : NEGV);
        r.y = pack2(m.z ? bv.z : NEGV, m.w ? bv.w : NEGV);
        a.bmh[i] = r;
    }
}

// ---------------------------------------------------------------------------
// GEMM body: pure-fp16, C = A@B * scale, fp32 accumulate. M=4096 N=K=1024.
// 128x128x32 tiles, 8 warps (2x4), m16n8k16 + ldmatrix, 3-stage cp.async.
// 3 CTAs/SM (reg cap 85) for latency hiding.
// HSPLIT: C is __half head-split layout [b][h][l][64]; else fp32 row-major.
// ---------------------------------------------------------------------------
#define GA_ST 40
#define GB_ST 136
#define GA_SZ (128 * GA_ST)
#define GB_SZ (32 * GB_ST)
#define GEMM_SMEM ((3 * GA_SZ + 3 * GB_SZ) * 2)

template <bool HSPLIT>
__device__ __forceinline__ void gemm_body(const __half* __restrict__ A,
                                          const __half* __restrict__ B,
                                          void* __restrict__ Cv, float scale) {
    extern __shared__ __half gsm[];
    const int K = DM, N = DM;
    const int tid = threadIdx.x, lane = tid & 31, wid = tid >> 5;
    const int g = lane >> 2, t4 = lane & 3;
    const int wm = wid >> 2, wn = wid & 3;
    const int row0 = blockIdx.y * 128, col0 = blockIdx.x * 128;
    const int arow = (lane & 7) + ((lane >> 3) & 1) * 8;
    const int acol = (lane >> 4) * 8;

    float acc[4][4][4];
#pragma unroll
    for (int m = 0; m < 4; m++)
#pragma unroll
        for (int n = 0; n < 4; n++)
#pragma unroll
            for (int i = 0; i < 4; i++) acc[m][n][i] = 0.f;

    auto issue = [&](int kt) {
        int buf = kt % 3;
        __half* As = gsm + buf * GA_SZ;
        __half* Bs = gsm + 3 * GA_SZ + buf * GB_SZ;
#pragma unroll
        for (int i = 0; i < 2; i++) {
            int f = tid + i * 256, r = f >> 2, c8 = (f & 3) * 8;
            cpa16(As + r * GA_ST + c8,
                  A + (size_t)(row0 + r) * K + kt * 32 + c8);
        }
#pragma unroll
        for (int i = 0; i < 2; i++) {
            int f = tid + i * 256, r = f >> 4, c8 = (f & 15) * 8;
            cpa16(Bs + r * GB_ST + c8,
                  B + (size_t)(kt * 32 + r) * N + col0 + c8);
        }
    };

    const int nk = K / 32;
    issue(0);
    CPCOMMIT;
    issue(1);
    CPCOMMIT;

    for (int kt = 0; kt < nk; kt++) {
        CPWAIT(1);
        __syncthreads();
        int buf = kt % 3;
        __half* As = gsm + buf * GA_SZ;
        __half* Bs = gsm + 3 * GA_SZ + buf * GB_SZ;
#pragma unroll
        for (int kk = 0; kk < 2; kk++) {
            unsigned af[4][4];
#pragma unroll
            for (int m = 0; m < 4; m++)
                ldsm4(af[m][0], af[m][1], af[m][2], af[m][3],
                      s2u(As + (wm * 64 + m * 16 + arow) * GA_ST + kk * 16 +
                          acol));
            unsigned bf[4][2];
#pragma unroll
            for (int np = 0; np < 2; np++) {
                unsigned r0, r1, r2, r3;
                ldsm4t(r0, r1, r2, r3,
                       s2u(Bs + (kk * 16 + arow) * GB_ST + wn * 32 + np * 16 +
                           acol));
                bf[np * 2][0] = r0;
                bf[np * 2][1] = r1;
                bf[np * 2 + 1][0] = r2;
                bf[np * 2 + 1][1] = r3;
            }
#pragma unroll
            for (int m = 0; m < 4; m++)
#pragma unroll
                for (int n = 0; n < 4; n++)
                    mma16(acc[m][n], af[m][0], af[m][1], af[m][2], af[m][3],
                          bf[n][0], bf[n][1]);
        }
        if (kt + 2 < nk) issue(kt + 2);
        CPCOMMIT;
    }

#pragma unroll
    for (int m = 0; m < 4; m++) {
#pragma unroll
        for (int n = 0; n < 4; n++) {
            int row = row0 + wm * 64 + m * 16 + g;
            int col = col0 + wn * 32 + n * 8 + 2 * t4;
            if (HSPLIT) {
                __half* C = (__half*)Cv;
                int b = row >> 11, l = row & (LL - 1);
                int h = col >> 6, d = col & 63;
                size_t idx = ((size_t)(b * NH + h) * LL + l) * 64 + d;
                *(__half2*)&C[idx] = __floats2half2_rn(acc[m][n][0] * scale,
                                                       acc[m][n][1] * scale);
                *(__half2*)&C[idx + (size_t)8 * 64] = __floats2half2_rn(
                    acc[m][n][2] * scale, acc[m][n][3] * scale);
            } else {
                float* C = (float*)Cv;
                size_t idx = (size_t)row * N + col;
                float2 v0 = {acc[m][n][0] * scale, acc[m][n][1] * scale};
                float2 v1 = {acc[m][n][2] * scale, acc[m][n][3] * scale};
                *(float2*)&C[idx] = v0;
                *(float2*)&C[idx + (size_t)8 * N] = v1;
            }
        }
    }
}

// Q/K/V projections in ONE launch: grid.z picks operands.
struct QKVArgs {
    const __half* A[3];
    const __half* B[3];
    __half* C[3];
    float scale[3];
};
__global__ __launch_bounds__(256, 3) void gemm_qkv(QKVArgs a) {
    int z = blockIdx.z;
    gemm_body<true>(a.A[z], a.B[z], a.C[z], a.scale[z]);
}

__global__ __launch_bounds__(256, 3) void gemm_out(const __half* __restrict__ A,
                                                   const __half* __restrict__ B,
                                                   float* __restrict__ C) {
    gemm_body<false>(A, B, C, 1.0f);
}

// ---------------------------------------------------------------------------
// Kernel 3: flash attention. CTA = (128 q rows, 1 head).
// P in registers; l via ones-column MMA; masking by plain add (underflow);
// BM fp16 gmem->regs (halves L2 traffic); K/V double-buffered cp.async.
// ---------------------------------------------------------------------------
#define KV_SZ (64 * 72)
#define ATTN_SMEM ((128 * 72 + 4 * KV_SZ) * 2)  // 55296 B

__global__ __launch_bounds__(256, 2) void attn_kernel() {
    extern __shared__ __half smh[];
    __half* Qs = smh;                  // [128][72]
    __half* Ksb = smh + 128 * 72;      // [2][64][72]
    __half* Vsb = Ksb + 2 * KV_SZ;     // [2][64][72]

    const int b = blockIdx.z, h = blockIdx.y, qt = blockIdx.x;
    const int tid = threadIdx.x, lane = tid & 31, wid = tid >> 5;
    const int g = lane >> 2, t4 = lane & 3;
    const int wrow = wid * 16;
    const int arow = (lane & 7) + ((lane >> 3) & 1) * 8;  // A-style / trans-B
    const int acol = (lane >> 4) * 8;
    const int brow = (lane & 7) + (lane >> 4) * 8;        // non-trans B (S)
    const int bcol = ((lane >> 3) & 1) * 8;
    // constant B fragment: ones in column n=0 -> row-sum of P via the MMA
    const unsigned bb = (g == 0) ? 0x3C003C00u : 0u;

    const __half* Qp = g_Qh + ((size_t)(b * NH + h) * LL + qt * TQ) * DKV;
    const __half* Kp = g_Kh + (size_t)(b * NH + h) * LL * DKV;
    const __half* Vp = g_Vh + (size_t)(b * NH + h) * LL * DKV;
    const __half* BMp = g_BMh + ((size_t)b * LL + qt * TQ) * LL;

    auto issue_kv = [&](int kt, int buf) {
#pragma unroll
        for (int i = 0; i < 2; i++) {
            int f = tid + i * 256, r = f >> 3, c8 = (f & 7) * 8;
            cpa16(Ksb + buf * KV_SZ + r * 72 + c8,
                  Kp + (size_t)(kt * TK + r) * 64 + c8);
            cpa16(Vsb + buf * KV_SZ + r * 72 + c8,
                  Vp + (size_t)(kt * TK + r) * 64 + c8);
        }
    };

    // Q tile (once) + first K/V tile, one cp.async group
#pragma unroll
    for (int i = 0; i < 4; i++) {
        int f = tid + i * 256, r = f >> 3, c8 = (f & 7) * 8;
        cpa16(Qs + r * 72 + c8, Qp + (size_t)r * 64 + c8);
    }
    issue_kv(0, 0);
    CPCOMMIT;

    float m_i[2] = {-1e30f, -1e30f};
    float lacc[4] = {0.f, 0.f, 0.f, 0.f};
    float oacc[8][4];
#pragma unroll
    for (int nf = 0; nf < 8; nf++)
#pragma unroll
        for (int i = 0; i < 4; i++) oacc[nf][i] = 0.f;

    for (int kt = 0; kt < NT; kt++) {
        int cur = kt & 1;
        CPWAIT(0);
        __syncthreads();
        if (kt + 1 < NT) {
            issue_kv(kt + 1, cur ^ 1);
            CPCOMMIT;
        }
        __half* Ks = Ksb + cur * KV_SZ;
        __half* Vs = Vsb + cur * KV_SZ;

        // BM batch 0 (nf 0..3): fp16 gmem -> regs, hidden under the S-mma
        __half2 bm[8];
#pragma unroll
        for (int nf = 0; nf < 4; nf++)
#pragma unroll
            for (int rr = 0; rr < 2; rr++)
                bm[nf * 2 + rr] = *(const __half2*)(
                    BMp + (size_t)(wrow + g + rr * 8) * LL + kt * TK + nf * 8 +
                    2 * t4);

        // S = Q @ K^T
        float sacc[8][4];
#pragma unroll
        for (int nf = 0; nf < 8; nf++)
#pragma unroll
            for (int i = 0; i < 4; i++) sacc[nf][i] = 0.f;
#pragma unroll
        for (int kk = 0; kk < 4; kk++) {
            unsigned a0, a1, a2, a3;
            ldsm4(a0, a1, a2, a3,
                  s2u(Qs + (wrow + arow) * 72 + kk * 16 + acol));
#pragma unroll
            for (int np = 0; np < 4; np++) {
                unsigned r0, r1, r2, r3;
                ldsm4(r0, r1, r2, r3,
                      s2u(Ks + (np * 16 + brow) * 72 + kk * 16 + bcol));
                mma16(sacc[np * 2], a0, a1, a2, a3, r0, r1);
                mma16(sacc[np * 2 + 1], a0, a1, a2, a3, r2, r3);
            }
        }

        // bias/mask: plain add (masked -> s-10000 -> exp underflows to 0,
        // matching the reference's replace-then-softmax exactly)
        float mloc[2] = {-1e30f, -1e30f};
#pragma unroll
        for (int nf = 0; nf < 4; nf++) {
#pragma unroll
            for (int rr = 0; rr < 2; rr++) {
                float2 bv = __half22float2(bm[nf * 2 + rr]);
                float s0 = sacc[nf][rr * 2 + 0] + bv.x;
                float s1 = sacc[nf][rr * 2 + 1] + bv.y;
                sacc[nf][rr * 2 + 0] = s0;
                sacc[nf][rr * 2 + 1] = s1;
                mloc[rr] = fmaxf(mloc[rr], fmaxf(s0, s1));
            }
        }
        // BM batch 1 (nf 4..7) reuses the same registers
#pragma unroll
        for (int nf = 0; nf < 4; nf++)
#pragma unroll
            for (int rr = 0; rr < 2; rr++)
                bm[nf * 2 + rr] = *(const __half2*)(
                    BMp + (size_t)(wrow + g + rr * 8) * LL + kt * TK +
                    (nf + 4) * 8 + 2 * t4);
#pragma unroll
        for (int nf = 4; nf < 8; nf++) {
#pragma unroll
            for (int rr = 0; rr < 2; rr++) {
                float2 bv = __half22float2(bm[(nf - 4) * 2 + rr]);
                float s0 = sacc[nf][rr * 2 + 0] + bv.x;
                float s1 = sacc[nf][rr * 2 + 1] + bv.y;
                sacc[nf][rr * 2 + 0] = s0;
                sacc[nf][rr * 2 + 1] = s1;
                mloc[rr] = fmaxf(mloc[rr], fmaxf(s0, s1));
            }
        }
#pragma unroll
        for (int rr = 0; rr < 2; rr++) {
            mloc[rr] = fmaxf(mloc[rr], __shfl_xor_sync(0xffffffffu, mloc[rr], 1));
            mloc[rr] = fmaxf(mloc[rr], __shfl_xor_sync(0xffffffffu, mloc[rr], 2));
        }
        float alpha[2], nmL[2];
#pragma unroll
        for (int rr = 0; rr < 2; rr++) {
            float mn = fmaxf(m_i[rr], mloc[rr]);
            alpha[rr] = ex2f((m_i[rr] - mn) * L2E);
            m_i[rr] = mn;
            nmL[rr] = -mn * L2E;
        }
        // P = exp2(s*log2e - m*log2e), packed straight to half2 A-fragments
        unsigned pk[16];
#pragma unroll
        for (int nf = 0; nf < 8; nf++) {
#pragma unroll
            for (int rr = 0; rr < 2; rr++) {
                float p0 = ex2f(fmaf(sacc[nf][rr * 2 + 0], L2E, nmL[rr]));
                float p1 = ex2f(fmaf(sacc[nf][rr * 2 + 1], L2E, nmL[rr]));
                pk[nf * 2 + rr] = pack2(p0, p1);
            }
        }
        // rescale running O and l by alpha
#pragma unroll
        for (int nf = 0; nf < 8; nf++) {
            oacc[nf][0] *= alpha[0];
            oacc[nf][1] *= alpha[0];
            oacc[nf][2] *= alpha[1];
            oacc[nf][3] *= alpha[1];
        }
        lacc[0] *= alpha[0];
        lacc[1] *= alpha[0];
        lacc[2] *= alpha[1];
        lacc[3] *= alpha[1];

        // O += P @ V ; l += P @ ones (constant B fragment, col 0)
#pragma unroll
        for (int kk = 0; kk < 4; kk++) {
            unsigned a0 = pk[4 * kk + 0], a1 = pk[4 * kk + 1];
            unsigned a2 = pk[4 * kk + 2], a3 = pk[4 * kk + 3];
            mma16(lacc, a0, a1, a2, a3, bb, bb);
#pragma unroll
            for (int np = 0; np < 4; np++) {
                unsigned r0, r1, r2, r3;
                ldsm4t(r0, r1, r2, r3,
                       s2u(Vs + (kk * 16 + arow) * 72 + np * 16 + acol));
                mma16(oacc[np * 2], a0, a1, a2, a3, r0, r1);
                mma16(oacc[np * 2 + 1], a0, a1, a2, a3, r2, r3);
            }
        }
    }

    // l lives in column 0 of the lacc fragment: threads t4==0, c0 (row g)
    // and c2 (row g+8). Broadcast within each quad.
    float l0 = __shfl_sync(0xffffffffu, lacc[0], lane & ~3);
    float l1 = __shfl_sync(0xffffffffu, lacc[2], lane & ~3);
    float inv0 = 1.f / l0, inv1 = 1.f / l1;
#pragma unroll
    for (int nf = 0; nf < 8; nf++) {
        int col = nf * 8 + 2 * t4;
        int row = qt * TQ + wrow + g;
        size_t idx = ((size_t)b * LL + row) * DM + h * DKV + col;
        *(__half2*)&g_O[idx] =
            __floats2half2_rn(oacc[nf][0] * inv0, oacc[nf][1] * inv0);
        *(__half2*)&g_O[idx + (size_t)8 * DM] =
            __floats2half2_rn(oacc[nf][2] * inv1, oacc[nf][3] * inv1);
    }
}

// ---------------------------------------------------------------------------
// Launch
// ---------------------------------------------------------------------------
extern "C" void kernel_launch(void* const* d_in, const int* in_sizes, int n_in,
                              void* d_out, int out_size) {
    float* out = (float*)d_out;

    __half *hq, *hk, *hv, *hw, *Qh, *Kh, *Vh, *O, *BMh;
    cudaGetSymbolAddress((void**)&hq, g_hq);
    cudaGetSymbolAddress((void**)&hk, g_hk);
    cudaGetSymbolAddress((void**)&hv, g_hv);
    cudaGetSymbolAddress((void**)&hw, g_hw);
    cudaGetSymbolAddress((void**)&Qh, g_Qh);
    cudaGetSymbolAddress((void**)&Kh, g_Kh);
    cudaGetSymbolAddress((void**)&Vh, g_Vh);
    cudaGetSymbolAddress((void**)&BMh, g_BMh);
    cudaGetSymbolAddress((void**)&O, g_O);
    size_t WSZ = (size_t)DM * DM;

    cudaFuncSetAttribute(attn_kernel,
                         cudaFuncAttributeMaxDynamicSharedMemorySize,
                         ATTN_SMEM);
    cudaFuncSetAttribute(gemm_qkv,
                         cudaFuncAttributeMaxDynamicSharedMemorySize,
                         GEMM_SMEM);
    cudaFuncSetAttribute(gemm_out,
                         cudaFuncAttributeMaxDynamicSharedMemorySize,
                         GEMM_SMEM);

    // 0. merged prep: fp32->fp16 converts + mask/bias fusion (BM as fp16)
    PrepArgs pa;
    pa.s[0] = (const float4*)d_in[0];
    pa.s[1] = (const float4*)d_in[1];
    pa.s[2] = (const float4*)d_in[2];
    pa.s[3] = (const float4*)d_in[5];
    pa.s[4] = (const float4*)d_in[6];
    pa.s[5] = (const float4*)d_in[7];
    pa.s[6] = (const float4*)d_in[8];
    pa.d[0] = (uint2*)hq;
    pa.d[1] = (uint2*)hk;
    pa.d[2] = (uint2*)hv;
    pa.d[3] = (uint2*)(hw + 0 * WSZ);
    pa.d[4] = (uint2*)(hw + 1 * WSZ);
    pa.d[5] = (uint2*)(hw + 2 * WSZ);
    pa.d[6] = (uint2*)(hw + 3 * WSZ);
    pa.mask = (const int4*)d_in[3];
    pa.bias = (const float4*)d_in[4];
    pa.bmh = (uint2*)BMh;
    prep_kernel<<<4096 + 8192, 256>>>(pa);

    // 1. Q/K/V projections in one launch (Q pre-scaled by 1/8)
    QKVArgs qa;
    qa.A[0] = hq;
    qa.A[1] = hk;
    qa.A[2] = hv;
    qa.B[0] = hw + 0 * WSZ;
    qa.B[1] = hw + 1 * WSZ;
    qa.B[2] = hw + 2 * WSZ;
    qa.C[0] = Qh;
    qa.C[1] = Kh;
    qa.C[2] = Vh;
    qa.scale[0] = 0.125f;
    qa.scale[1] = 1.0f;
    qa.scale[2] = 1.0f;
    gemm_qkv<<<dim3(DM / 128, (BB * LL) / 128, 3), 256, GEMM_SMEM>>>(qa);

    // 2. attention
    attn_kernel<<<dim3(LL / TQ, NH, BB), 256, ATTN_SMEM>>>();

    // 3. output projection (half in, fp32 out)
    gemm_out<<<dim3(DM / 128, (BB * LL) / 128), 256, GEMM_SMEM>>>(
        O, hw + 3 * WSZ, out);
}

// round 14
// speedup vs baseline: 1.7094x; 1.7094x over previous
#include <cuda_runtime.h>
#include <cuda_fp16.h>

#define BB 2
#define LL 2048
#define DM 1024
#define NH 16
#define DKV 64
#define NEGV (-10000.0f)
#define TQ 128
#define TK 64
#define NT (LL / TK)
#define L2E 1.4426950408889634f

// Scratch (device globals: allocation-free per harness rules)
__device__ __align__(16) __half g_hq[(size_t)BB * LL * DM];
__device__ __align__(16) __half g_hk[(size_t)BB * LL * DM];
__device__ __align__(16) __half g_hv[(size_t)BB * LL * DM];
__device__ __align__(16) __half g_hw[4][(size_t)DM * DM];
__device__ __align__(16) __half g_Qh[(size_t)BB * NH * LL * DKV];
__device__ __align__(16) __half g_Kh[(size_t)BB * NH * LL * DKV];
__device__ __align__(16) __half g_Vh[(size_t)BB * NH * LL * DKV];
__device__ __align__(16) __half g_BMh[(size_t)BB * LL * LL];
__device__ __align__(16) __half g_O[(size_t)BB * LL * DM];

__device__ __forceinline__ unsigned pack2(float x, float y) {
    __half2 h = __floats2half2_rn(x, y);
    return *reinterpret_cast<unsigned*>(&h);
}

__device__ __forceinline__ float ex2f(float x) {
    float y;
    asm("ex2.approx.f32 %0,%1;" : "=f"(y) : "f"(x));
    return y;
}

__device__ __forceinline__ unsigned s2u(const void* p) {
    return (unsigned)__cvta_generic_to_shared(p);
}

__device__ __forceinline__ void cpa16(void* dst, const void* src) {
    asm volatile("cp.async.cg.shared.global [%0],[%1],16;" ::"r"(s2u(dst)),
                 "l"(src));
}
#define CPCOMMIT asm volatile("cp.async.commit_group;")
#define CPWAIT(n) asm volatile("cp.async.wait_group %0;" ::"n"(n))

__device__ __forceinline__ void ldsm4(unsigned& r0, unsigned& r1, unsigned& r2,
                                      unsigned& r3, unsigned addr) {
    asm volatile("ldmatrix.sync.aligned.m8n8.x4.shared.b16 {%0,%1,%2,%3},[%4];"
                 : "=r"(r0), "=r"(r1), "=r"(r2), "=r"(r3)
                 : "r"(addr));
}

__device__ __forceinline__ void ldsm4t(unsigned& r0, unsigned& r1, unsigned& r2,
                                       unsigned& r3, unsigned addr) {
    asm volatile(
        "ldmatrix.sync.aligned.m8n8.x4.trans.shared.b16 {%0,%1,%2,%3},[%4];"
        : "=r"(r0), "=r"(r1), "=r"(r2), "=r"(r3)
        : "r"(addr));
}

__device__ __forceinline__ void mma16(float* c, unsigned a0, unsigned a1,
                                      unsigned a2, unsigned a3, unsigned b0,
                                      unsigned b1) {
    asm volatile(
        "mma.sync.aligned.m16n8k16.row.col.f32.f16.f16.f32 "
        "{%0,%1,%2,%3},{%4,%5,%6,%7},{%8,%9},{%0,%1,%2,%3};"
        : "+f"(c[0]), "+f"(c[1]), "+f"(c[2]), "+f"(c[3])
        : "r"(a0), "r"(a1), "r"(a2), "r"(a3), "r"(b0), "r"(b1));
}

// ---------------------------------------------------------------------------
// Kernel 0: merged prep. Blocks [0,4096): fp32->fp16 convert of activations
// + weights. Blocks [4096,12288): fuse mask+bias -> BM (fp16; -10000 is
// exactly representable in half so masking semantics are preserved).
// ---------------------------------------------------------------------------
struct PrepArgs {
    const float4* s[7];
    uint2* d[7];
    const int4* mask;
    const float4* bias;
    uint2* bmh;
};
__global__ __launch_bounds__(256) void prep_kernel(PrepArgs a) {
    int bid = blockIdx.x;
    if (bid < 4096) {
        int ti, base;
        if (bid < 3072) {
            ti = bid >> 10;
            base = bid & 1023;
        } else {
            ti = 3 + ((bid - 3072) >> 8);
            base = (bid - 3072) & 255;
        }
        const float4* s = a.s[ti];
        uint2* d = a.d[ti];
        size_t off = (size_t)base * 1024 + threadIdx.x;
#pragma unroll
        for (int i = 0; i < 4; i++) {
            float4 v = s[off + i * 256];
            uint2 u;
            u.x = pack2(v.x, v.y);
            u.y = pack2(v.z, v.w);
            d[off + i * 256] = u;
        }
    } else {
        size_t i = (size_t)(bid - 4096) * 256 + threadIdx.x;
        int4 m = a.mask[i];
        float4 bv = a.bias[i];
        uint2 r;
        r.x = pack2(m.x ? bv.x : NEGV, m.y ? bv.y : NEGV);
        r.y = pack2(m.z ? bv.z : NEGV, m.w ? bv.w : NEGV);
        a.bmh[i] = r;
    }
}

// ---------------------------------------------------------------------------
// GEMM body: pure-fp16, C = A@B * scale, fp32 accumulate. M=4096 N=K=1024.
// 128x128x32 tiles, 8 warps (2x4), m16n8k16 + ldmatrix, 3-stage cp.async.
// Plain launch_bounds(256): 94 regs, NO spill (the (256,3) cap of 80 regs
// spilled the accumulators and cost 2x — R12 post-mortem).
// HSPLIT: C is __half head-split layout [b][h][l][64]; else fp32 row-major.
// ---------------------------------------------------------------------------
#define GA_ST 40
#define GB_ST 136
#define GA_SZ (128 * GA_ST)
#define GB_SZ (32 * GB_ST)
#define GEMM_SMEM ((3 * GA_SZ + 3 * GB_SZ) * 2)

template <bool HSPLIT>
__device__ __forceinline__ void gemm_body(const __half* __restrict__ A,
                                          const __half* __restrict__ B,
                                          void* __restrict__ Cv, float scale) {
    extern __shared__ __half gsm[];
    const int K = DM, N = DM;
    const int tid = threadIdx.x, lane = tid & 31, wid = tid >> 5;
    const int g = lane >> 2, t4 = lane & 3;
    const int wm = wid >> 2, wn = wid & 3;
    const int row0 = blockIdx.y * 128, col0 = blockIdx.x * 128;
    const int arow = (lane & 7) + ((lane >> 3) & 1) * 8;
    const int acol = (lane >> 4) * 8;

    float acc[4][4][4];
#pragma unroll
    for (int m = 0; m < 4; m++)
#pragma unroll
        for (int n = 0; n < 4; n++)
#pragma unroll
            for (int i = 0; i < 4; i++) acc[m][n][i] = 0.f;

    auto issue = [&](int kt) {
        int buf = kt % 3;
        __half* As = gsm + buf * GA_SZ;
        __half* Bs = gsm + 3 * GA_SZ + buf * GB_SZ;
#pragma unroll
        for (int i = 0; i < 2; i++) {
            int f = tid + i * 256, r = f >> 2, c8 = (f & 3) * 8;
            cpa16(As + r * GA_ST + c8,
                  A + (size_t)(row0 + r) * K + kt * 32 + c8);
        }
#pragma unroll
        for (int i = 0; i < 2; i++) {
            int f = tid + i * 256, r = f >> 4, c8 = (f & 15) * 8;
            cpa16(Bs + r * GB_ST + c8,
                  B + (size_t)(kt * 32 + r) * N + col0 + c8);
        }
    };

    const int nk = K / 32;
    issue(0);
    CPCOMMIT;
    issue(1);
    CPCOMMIT;

    for (int kt = 0; kt < nk; kt++) {
        CPWAIT(1);
        __syncthreads();
        int buf = kt % 3;
        __half* As = gsm + buf * GA_SZ;
        __half* Bs = gsm + 3 * GA_SZ + buf * GB_SZ;
#pragma unroll
        for (int kk = 0; kk < 2; kk++) {
            unsigned af[4][4];
#pragma unroll
            for (int m = 0; m < 4; m++)
                ldsm4(af[m][0], af[m][1], af[m][2], af[m][3],
                      s2u(As + (wm * 64 + m * 16 + arow) * GA_ST + kk * 16 +
                          acol));
            unsigned bf[4][2];
#pragma unroll
            for (int np = 0; np < 2; np++) {
                unsigned r0, r1, r2, r3;
                ldsm4t(r0, r1, r2, r3,
                       s2u(Bs + (kk * 16 + arow) * GB_ST + wn * 32 + np * 16 +
                           acol));
                bf[np * 2][0] = r0;
                bf[np * 2][1] = r1;
                bf[np * 2 + 1][0] = r2;
                bf[np * 2 + 1][1] = r3;
            }
#pragma unroll
            for (int m = 0; m < 4; m++)
#pragma unroll
                for (int n = 0; n < 4; n++)
                    mma16(acc[m][n], af[m][0], af[m][1], af[m][2], af[m][3],
                          bf[n][0], bf[n][1]);
        }
        if (kt + 2 < nk) issue(kt + 2);
        CPCOMMIT;
    }

#pragma unroll
    for (int m = 0; m < 4; m++) {
#pragma unroll
        for (int n = 0; n < 4; n++) {
            int row = row0 + wm * 64 + m * 16 + g;
            int col = col0 + wn * 32 + n * 8 + 2 * t4;
            if (HSPLIT) {
                __half* C = (__half*)Cv;
                int b = row >> 11, l = row & (LL - 1);
                int h = col >> 6, d = col & 63;
                size_t idx = ((size_t)(b * NH + h) * LL + l) * 64 + d;
                *(__half2*)&C[idx] = __floats2half2_rn(acc[m][n][0] * scale,
                                                       acc[m][n][1] * scale);
                *(__half2*)&C[idx + (size_t)8 * 64] = __floats2half2_rn(
                    acc[m][n][2] * scale, acc[m][n][3] * scale);
            } else {
                float* C = (float*)Cv;
                size_t idx = (size_t)row * N + col;
                float2 v0 = {acc[m][n][0] * scale, acc[m][n][1] * scale};
                float2 v1 = {acc[m][n][2] * scale, acc[m][n][3] * scale};
                *(float2*)&C[idx] = v0;
                *(float2*)&C[idx + (size_t)8 * N] = v1;
            }
        }
    }
}

// Q/K/V projections in ONE launch: grid.z picks operands.
struct QKVArgs {
    const __half* A[3];
    const __half* B[3];
    __half* C[3];
    float scale[3];
};
__global__ __launch_bounds__(256) void gemm_qkv(QKVArgs a) {
    int z = blockIdx.z;
    gemm_body<true>(a.A[z], a.B[z], a.C[z], a.scale[z]);
}

__global__ __launch_bounds__(256) void gemm_out(const __half* __restrict__ A,
                                                const __half* __restrict__ B,
                                                float* __restrict__ C) {
    gemm_body<false>(A, B, C, 1.0f);
}

// ---------------------------------------------------------------------------
// Kernel 3: flash attention. CTA = (128 q rows, 1 head).
// P in registers; l via ones-column MMA; masking by plain add (underflow);
// BM fp16 gmem->regs (halves L2 traffic); K/V double-buffered cp.async.
// ---------------------------------------------------------------------------
#define KV_SZ (64 * 72)
#define ATTN_SMEM ((128 * 72 + 4 * KV_SZ) * 2)  // 55296 B

__global__ __launch_bounds__(256, 2) void attn_kernel() {
    extern __shared__ __half smh[];
    __half* Qs = smh;                  // [128][72]
    __half* Ksb = smh + 128 * 72;      // [2][64][72]
    __half* Vsb = Ksb + 2 * KV_SZ;     // [2][64][72]

    const int b = blockIdx.z, h = blockIdx.y, qt = blockIdx.x;
    const int tid = threadIdx.x, lane = tid & 31, wid = tid >> 5;
    const int g = lane >> 2, t4 = lane & 3;
    const int wrow = wid * 16;
    const int arow = (lane & 7) + ((lane >> 3) & 1) * 8;  // A-style / trans-B
    const int acol = (lane >> 4) * 8;
    const int brow = (lane & 7) + (lane >> 4) * 8;        // non-trans B (S)
    const int bcol = ((lane >> 3) & 1) * 8;
    // constant B fragment: ones in column n=0 -> row-sum of P via the MMA
    const unsigned bb = (g == 0) ? 0x3C003C00u : 0u;

    const __half* Qp = g_Qh + ((size_t)(b * NH + h) * LL + qt * TQ) * DKV;
    const __half* Kp = g_Kh + (size_t)(b * NH + h) * LL * DKV;
    const __half* Vp = g_Vh + (size_t)(b * NH + h) * LL * DKV;
    const __half* BMp = g_BMh + ((size_t)b * LL + qt * TQ) * LL;

    auto issue_kv = [&](int kt, int buf) {
#pragma unroll
        for (int i = 0; i < 2; i++) {
            int f = tid + i * 256, r = f >> 3, c8 = (f & 7) * 8;
            cpa16(Ksb + buf * KV_SZ + r * 72 + c8,
                  Kp + (size_t)(kt * TK + r) * 64 + c8);
            cpa16(Vsb + buf * KV_SZ + r * 72 + c8,
                  Vp + (size_t)(kt * TK + r) * 64 + c8);
        }
    };

    // Q tile (once) + first K/V tile, one cp.async group
#pragma unroll
    for (int i = 0; i < 4; i++) {
        int f = tid + i * 256, r = f >> 3, c8 = (f & 7) * 8;
        cpa16(Qs + r * 72 + c8, Qp + (size_t)r * 64 + c8);
    }
    issue_kv(0, 0);
    CPCOMMIT;

    float m_i[2] = {-1e30f, -1e30f};
    float lacc[4] = {0.f, 0.f, 0.f, 0.f};
    float oacc[8][4];
#pragma unroll
    for (int nf = 0; nf < 8; nf++)
#pragma unroll
        for (int i = 0; i < 4; i++) oacc[nf][i] = 0.f;

    for (int kt = 0; kt < NT; kt++) {
        int cur = kt & 1;
        CPWAIT(0);
        __syncthreads();
        if (kt + 1 < NT) {
            issue_kv(kt + 1, cur ^ 1);
            CPCOMMIT;
        }
        __half* Ks = Ksb + cur * KV_SZ;
        __half* Vs = Vsb + cur * KV_SZ;

        // BM batch 0 (nf 0..3): fp16 gmem -> regs, hidden under the S-mma
        __half2 bm[8];
#pragma unroll
        for (int nf = 0; nf < 4; nf++)
#pragma unroll
            for (int rr = 0; rr < 2; rr++)
                bm[nf * 2 + rr] = *(const __half2*)(
                    BMp + (size_t)(wrow + g + rr * 8) * LL + kt * TK + nf * 8 +
                    2 * t4);

        // S = Q @ K^T
        float sacc[8][4];
#pragma unroll
        for (int nf = 0; nf < 8; nf++)
#pragma unroll
            for (int i = 0; i < 4; i++) sacc[nf][i] = 0.f;
#pragma unroll
        for (int kk = 0; kk < 4; kk++) {
            unsigned a0, a1, a2, a3;
            ldsm4(a0, a1, a2, a3,
                  s2u(Qs + (wrow + arow) * 72 + kk * 16 + acol));
#pragma unroll
            for (int np = 0; np < 4; np++) {
                unsigned r0, r1, r2, r3;
                ldsm4(r0, r1, r2, r3,
                      s2u(Ks + (np * 16 + brow) * 72 + kk * 16 + bcol));
                mma16(sacc[np * 2], a0, a1, a2, a3, r0, r1);
                mma16(sacc[np * 2 + 1], a0, a1, a2, a3, r2, r3);
            }
        }

        // bias/mask: plain add (masked -> s-10000 -> exp underflows to 0,
        // matching the reference's replace-then-softmax exactly)
        float mloc[2] = {-1e30f, -1e30f};
#pragma unroll
        for (int nf = 0; nf < 4; nf++) {
#pragma unroll
            for (int rr = 0; rr < 2; rr++) {
                float2 bv = __half22float2(bm[nf * 2 + rr]);
                float s0 = sacc[nf][rr * 2 + 0] + bv.x;
                float s1 = sacc[nf][rr * 2 + 1] + bv.y;
                sacc[nf][rr * 2 + 0] = s0;
                sacc[nf][rr * 2 + 1] = s1;
                mloc[rr] = fmaxf(mloc[rr], fmaxf(s0, s1));
            }
        }
        // BM batch 1 (nf 4..7) reuses the same registers
#pragma unroll
        for (int nf = 0; nf < 4; nf++)
#pragma unroll
            for (int rr = 0; rr < 2; rr++)
                bm[nf * 2 + rr] = *(const __half2*)(
                    BMp + (size_t)(wrow + g + rr * 8) * LL + kt * TK +
                    (nf + 4) * 8 + 2 * t4);
#pragma unroll
        for (int nf = 4; nf < 8; nf++) {
#pragma unroll
            for (int rr = 0; rr < 2; rr++) {
                float2 bv = __half22float2(bm[(nf - 4) * 2 + rr]);
                float s0 = sacc[nf][rr * 2 + 0] + bv.x;
                float s1 = sacc[nf][rr * 2 + 1] + bv.y;
                sacc[nf][rr * 2 + 0] = s0;
                sacc[nf][rr * 2 + 1] = s1;
                mloc[rr] = fmaxf(mloc[rr], fmaxf(s0, s1));
            }
        }
#pragma unroll
        for (int rr = 0; rr < 2; rr++) {
            mloc[rr] = fmaxf(mloc[rr], __shfl_xor_sync(0xffffffffu, mloc[rr], 1));
            mloc[rr] = fmaxf(mloc[rr], __shfl_xor_sync(0xffffffffu, mloc[rr], 2));
        }
        float alpha[2], nmL[2];
#pragma unroll
        for (int rr = 0; rr < 2; rr++) {
            float mn = fmaxf(m_i[rr], mloc[rr]);
            alpha[rr] = ex2f((m_i[rr] - mn) * L2E);
            m_i[rr] = mn;
            nmL[rr] = -mn * L2E;
        }
        // P = exp2(s*log2e - m*log2e), packed straight to half2 A-fragments
        unsigned pk[16];
#pragma unroll
        for (int nf = 0; nf < 8; nf++) {
#pragma unroll
            for (int rr = 0; rr < 2; rr++) {
                float p0 = ex2f(fmaf(sacc[nf][rr * 2 + 0], L2E, nmL[rr]));
                float p1 = ex2f(fmaf(sacc[nf][rr * 2 + 1], L2E, nmL[rr]));
                pk[nf * 2 + rr] = pack2(p0, p1);
            }
        }
        // rescale running O and l by alpha
#pragma unroll
        for (int nf = 0; nf < 8; nf++) {
            oacc[nf][0] *= alpha[0];
            oacc[nf][1] *= alpha[0];
            oacc[nf][2] *= alpha[1];
            oacc[nf][3] *= alpha[1];
        }
        lacc[0] *= alpha[0];
        lacc[1] *= alpha[0];
        lacc[2] *= alpha[1];
        lacc[3] *= alpha[1];

        // O += P @ V ; l += P @ ones (constant B fragment, col 0)
#pragma unroll
        for (int kk = 0; kk < 4; kk++) {
            unsigned a0 = pk[4 * kk + 0], a1 = pk[4 * kk + 1];
            unsigned a2 = pk[4 * kk + 2], a3 = pk[4 * kk + 3];
            mma16(lacc, a0, a1, a2, a3, bb, bb);
#pragma unroll
            for (int np = 0; np < 4; np++) {
                unsigned r0, r1, r2, r3;
                ldsm4t(r0, r1, r2, r3,
                       s2u(Vs + (kk * 16 + arow) * 72 + np * 16 + acol));
                mma16(oacc[np * 2], a0, a1, a2, a3, r0, r1);
                mma16(oacc[np * 2 + 1], a0, a1, a2, a3, r2, r3);
            }
        }
    }

    // l lives in column 0 of the lacc fragment: threads t4==0, c0 (row g)
    // and c2 (row g+8). Broadcast within each quad.
    float l0 = __shfl_sync(0xffffffffu, lacc[0], lane & ~3);
    float l1 = __shfl_sync(0xffffffffu, lacc[2], lane & ~3);
    float inv0 = 1.f / l0, inv1 = 1.f / l1;
#pragma unroll
    for (int nf = 0; nf < 8; nf++) {
        int col = nf * 8 + 2 * t4;
        int row = qt * TQ + wrow + g;
        size_t idx = ((size_t)b * LL + row) * DM + h * DKV + col;
        *(__half2*)&g_O[idx] =
            __floats2half2_rn(oacc[nf][0] * inv0, oacc[nf][1] * inv0);
        *(__half2*)&g_O[idx + (size_t)8 * DM] =
            __floats2half2_rn(oacc[nf][2] * inv1, oacc[nf][3] * inv1);
    }
}

// ---------------------------------------------------------------------------
// Launch
// ---------------------------------------------------------------------------
extern "C" void kernel_launch(void* const* d_in, const int* in_sizes, int n_in,
                              void* d_out, int out_size) {
    float* out = (float*)d_out;

    __half *hq, *hk, *hv, *hw, *Qh, *Kh, *Vh, *O, *BMh;
    cudaGetSymbolAddress((void**)&hq, g_hq);
    cudaGetSymbolAddress((void**)&hk, g_hk);
    cudaGetSymbolAddress((void**)&hv, g_hv);
    cudaGetSymbolAddress((void**)&hw, g_hw);
    cudaGetSymbolAddress((void**)&Qh, g_Qh);
    cudaGetSymbolAddress((void**)&Kh, g_Kh);
    cudaGetSymbolAddress((void**)&Vh, g_Vh);
    cudaGetSymbolAddress((void**)&BMh, g_BMh);
    cudaGetSymbolAddress((void**)&O, g_O);
    size_t WSZ = (size_t)DM * DM;

    cudaFuncSetAttribute(attn_kernel,
                         cudaFuncAttributeMaxDynamicSharedMemorySize,
                         ATTN_SMEM);
    cudaFuncSetAttribute(gemm_qkv,
                         cudaFuncAttributeMaxDynamicSharedMemorySize,
                         GEMM_SMEM);
    cudaFuncSetAttribute(gemm_out,
                         cudaFuncAttributeMaxDynamicSharedMemorySize,
                         GEMM_SMEM);

    // 0. merged prep: fp32->fp16 converts + mask/bias fusion (BM as fp16)
    PrepArgs pa;
    pa.s[0] = (const float4*)d_in[0];
    pa.s[1] = (const float4*)d_in[1];
    pa.s[2] = (const float4*)d_in[2];
    pa.s[3] = (const float4*)d_in[5];
    pa.s[4] = (const float4*)d_in[6];
    pa.s[5] = (const float4*)d_in[7];
    pa.s[6] = (const float4*)d_in[8];
    pa.d[0] = (uint2*)hq;
    pa.d[1] = (uint2*)hk;
    pa.d[2] = (uint2*)hv;
    pa.d[3] = (uint2*)(hw + 0 * WSZ);
    pa.d[4] = (uint2*)(hw + 1 * WSZ);
    pa.d[5] = (uint2*)(hw + 2 * WSZ);
    pa.d[6] = (uint2*)(hw + 3 * WSZ);
    pa.mask = (const int4*)d_in[3];
    pa.bias = (const float4*)d_in[4];
    pa.bmh = (uint2*)BMh;
    prep_kernel<<<4096 + 8192, 256>>>(pa);

    // 1. Q/K/V projections in one launch (Q pre-scaled by 1/8)
    QKVArgs qa;
    qa.A[0] = hq;
    qa.A[1] = hk;
    qa.A[2] = hv;
    qa.B[0] = hw + 0 * WSZ;
    qa.B[1] = hw + 1 * WSZ;
    qa.B[2] = hw + 2 * WSZ;
    qa.C[0] = Qh;
    qa.C[1] = Kh;
    qa.C[2] = Vh;
    qa.scale[0] = 0.125f;
    qa.scale[1] = 1.0f;
    qa.scale[2] = 1.0f;
    gemm_qkv<<<dim3(DM / 128, (BB * LL) / 128, 3), 256, GEMM_SMEM>>>(qa);

    // 2. attention
    attn_kernel<<<dim3(LL / TQ, NH, BB), 256, ATTN_SMEM>>>();

    // 3. output projection (half in, fp32 out)
    gemm_out<<<dim3(DM / 128, (BB * LL) / 128), 256, GEMM_SMEM>>>(
        O, hw + 3 * WSZ, out);
}

// round 15
// speedup vs baseline: 1.7203x; 1.0064x over previous
#include <cuda_runtime.h>
#include <cuda_fp16.h>

#define BB 2
#define LL 2048
#define DM 1024
#define NH 16
#define DKV 64
#define NEGV (-10000.0f)
#define TQ 128
#define TK 64
#define NT (LL / TK)
#define L2E 1.4426950408889634f

// Scratch (device globals: allocation-free per harness rules)
__device__ __align__(16) __half g_hq[(size_t)BB * LL * DM];
__device__ __align__(16) __half g_hk[(size_t)BB * LL * DM];
__device__ __align__(16) __half g_hv[(size_t)BB * LL * DM];
__device__ __align__(16) __half g_hw[4][(size_t)DM * DM];
__device__ __align__(16) __half g_Qh[(size_t)BB * NH * LL * DKV];
__device__ __align__(16) __half g_Kh[(size_t)BB * NH * LL * DKV];
__device__ __align__(16) __half g_Vh[(size_t)BB * NH * LL * DKV];
__device__ __align__(16) __half g_BMh[(size_t)BB * LL * LL];
__device__ __align__(16) __half g_O[(size_t)BB * LL * DM];

__device__ __forceinline__ unsigned pack2(float x, float y) {
    __half2 h = __floats2half2_rn(x, y);
    return *reinterpret_cast<unsigned*>(&h);
}

__device__ __forceinline__ float ex2f(float x) {
    float y;
    asm("ex2.approx.f32 %0,%1;" : "=f"(y) : "f"(x));
    return y;
}

__device__ __forceinline__ unsigned s2u(const void* p) {
    return (unsigned)__cvta_generic_to_shared(p);
}

__device__ __forceinline__ void cpa16(void* dst, const void* src) {
    asm volatile("cp.async.cg.shared.global [%0],[%1],16;" ::"r"(s2u(dst)),
                 "l"(src));
}
#define CPCOMMIT asm volatile("cp.async.commit_group;")
#define CPWAIT(n) asm volatile("cp.async.wait_group %0;" ::"n"(n))

__device__ __forceinline__ void ldsm4(unsigned& r0, unsigned& r1, unsigned& r2,
                                      unsigned& r3, unsigned addr) {
    asm volatile("ldmatrix.sync.aligned.m8n8.x4.shared.b16 {%0,%1,%2,%3},[%4];"
                 : "=r"(r0), "=r"(r1), "=r"(r2), "=r"(r3)
                 : "r"(addr));
}

__device__ __forceinline__ void ldsm4t(unsigned& r0, unsigned& r1, unsigned& r2,
                                       unsigned& r3, unsigned addr) {
    asm volatile(
        "ldmatrix.sync.aligned.m8n8.x4.trans.shared.b16 {%0,%1,%2,%3},[%4];"
        : "=r"(r0), "=r"(r1), "=r"(r2), "=r"(r3)
        : "r"(addr));
}

__device__ __forceinline__ void mma16(float* c, unsigned a0, unsigned a1,
                                      unsigned a2, unsigned a3, unsigned b0,
                                      unsigned b1) {
    asm volatile(
        "mma.sync.aligned.m16n8k16.row.col.f32.f16.f16.f32 "
        "{%0,%1,%2,%3},{%4,%5,%6,%7},{%8,%9},{%0,%1,%2,%3};"
        : "+f"(c[0]), "+f"(c[1]), "+f"(c[2]), "+f"(c[3])
        : "r"(a0), "r"(a1), "r"(a2), "r"(a3), "r"(b0), "r"(b1));
}

// ---------------------------------------------------------------------------
// Kernel 0: merged prep. Blocks [0,4096): fp32->fp16 convert of activations
// + weights. Blocks [4096,12288): fuse mask+bias -> BM (fp16; -10000 is
// exactly representable in half so masking semantics are preserved).
// ---------------------------------------------------------------------------
struct PrepArgs {
    const float4* s[7];
    uint2* d[7];
    const int4* mask;
    const float4* bias;
    uint2* bmh;
};
__global__ __launch_bounds__(256) void prep_kernel(PrepArgs a) {
    int bid = blockIdx.x;
    if (bid < 4096) {
        int ti, base;
        if (bid < 3072) {
            ti = bid >> 10;
            base = bid & 1023;
        } else {
            ti = 3 + ((bid - 3072) >> 8);
            base = (bid - 3072) & 255;
        }
        const float4* s = a.s[ti];
        uint2* d = a.d[ti];
        size_t off = (size_t)base * 1024 + threadIdx.x;
#pragma unroll
        for (int i = 0; i < 4; i++) {
            float4 v = s[off + i * 256];
            uint2 u;
            u.x = pack2(v.x, v.y);
            u.y = pack2(v.z, v.w);
            d[off + i * 256] = u;
        }
    } else {
        size_t i = (size_t)(bid - 4096) * 256 + threadIdx.x;
        int4 m = a.mask[i];
        float4 bv = a.bias[i];
        uint2 r;
        r.x = pack2(m.x ? bv.x : NEGV, m.y ? bv.y : NEGV);
        r.y = pack2(m.z ? bv.z : NEGV, m.w ? bv.w : NEGV);
        a.bmh[i] = r;
    }
}

// ---------------------------------------------------------------------------
// GEMM body: pure-fp16, C = A@B * scale, fp32 accumulate. M=4096 N=K=1024.
// 128x128x32 tiles, 8 warps (2x4), m16n8k16 + ldmatrix, 3-stage cp.async.
// Plain launch_bounds(256): 94 regs, NO spill.
// HSPLIT: C is __half head-split layout [b][h][l][64]; else fp32 row-major.
// ---------------------------------------------------------------------------
#define GA_ST 40
#define GB_ST 136
#define GA_SZ (128 * GA_ST)
#define GB_SZ (32 * GB_ST)
#define GEMM_SMEM ((3 * GA_SZ + 3 * GB_SZ) * 2)

template <bool HSPLIT>
__device__ __forceinline__ void gemm_body(const __half* __restrict__ A,
                                          const __half* __restrict__ B,
                                          void* __restrict__ Cv, float scale) {
    extern __shared__ __half gsm[];
    const int K = DM, N = DM;
    const int tid = threadIdx.x, lane = tid & 31, wid = tid >> 5;
    const int g = lane >> 2, t4 = lane & 3;
    const int wm = wid >> 2, wn = wid & 3;
    const int row0 = blockIdx.y * 128, col0 = blockIdx.x * 128;
    const int arow = (lane & 7) + ((lane >> 3) & 1) * 8;
    const int acol = (lane >> 4) * 8;

    float acc[4][4][4];
#pragma unroll
    for (int m = 0; m < 4; m++)
#pragma unroll
        for (int n = 0; n < 4; n++)
#pragma unroll
            for (int i = 0; i < 4; i++) acc[m][n][i] = 0.f;

    auto issue = [&](int kt) {
        int buf = kt % 3;
        __half* As = gsm + buf * GA_SZ;
        __half* Bs = gsm + 3 * GA_SZ + buf * GB_SZ;
#pragma unroll
        for (int i = 0; i < 2; i++) {
            int f = tid + i * 256, r = f >> 2, c8 = (f & 3) * 8;
            cpa16(As + r * GA_ST + c8,
                  A + (size_t)(row0 + r) * K + kt * 32 + c8);
        }
#pragma unroll
        for (int i = 0; i < 2; i++) {
            int f = tid + i * 256, r = f >> 4, c8 = (f & 15) * 8;
            cpa16(Bs + r * GB_ST + c8,
                  B + (size_t)(kt * 32 + r) * N + col0 + c8);
        }
    };

    const int nk = K / 32;
    issue(0);
    CPCOMMIT;
    issue(1);
    CPCOMMIT;

    for (int kt = 0; kt < nk; kt++) {
        CPWAIT(1);
        __syncthreads();
        int buf = kt % 3;
        __half* As = gsm + buf * GA_SZ;
        __half* Bs = gsm + 3 * GA_SZ + buf * GB_SZ;
#pragma unroll
        for (int kk = 0; kk < 2; kk++) {
            unsigned af[4][4];
#pragma unroll
            for (int m = 0; m < 4; m++)
                ldsm4(af[m][0], af[m][1], af[m][2], af[m][3],
                      s2u(As + (wm * 64 + m * 16 + arow) * GA_ST + kk * 16 +
                          acol));
            unsigned bf[4][2];
#pragma unroll
            for (int np = 0; np < 2; np++) {
                unsigned r0, r1, r2, r3;
                ldsm4t(r0, r1, r2, r3,
                       s2u(Bs + (kk * 16 + arow) * GB_ST + wn * 32 + np * 16 +
                           acol));
                bf[np * 2][0] = r0;
                bf[np * 2][1] = r1;
                bf[np * 2 + 1][0] = r2;
                bf[np * 2 + 1][1] = r3;
            }
#pragma unroll
            for (int m = 0; m < 4; m++)
#pragma unroll
                for (int n = 0; n < 4; n++)
                    mma16(acc[m][n], af[m][0], af[m][1], af[m][2], af[m][3],
                          bf[n][0], bf[n][1]);
        }
        if (kt + 2 < nk) issue(kt + 2);
        CPCOMMIT;
    }

#pragma unroll
    for (int m = 0; m < 4; m++) {
#pragma unroll
        for (int n = 0; n < 4; n++) {
            int row = row0 + wm * 64 + m * 16 + g;
            int col = col0 + wn * 32 + n * 8 + 2 * t4;
            if (HSPLIT) {
                __half* C = (__half*)Cv;
                int b = row >> 11, l = row & (LL - 1);
                int h = col >> 6, d = col & 63;
                size_t idx = ((size_t)(b * NH + h) * LL + l) * 64 + d;
                *(__half2*)&C[idx] = __floats2half2_rn(acc[m][n][0] * scale,
                                                       acc[m][n][1] * scale);
                *(__half2*)&C[idx + (size_t)8 * 64] = __floats2half2_rn(
                    acc[m][n][2] * scale, acc[m][n][3] * scale);
            } else {
                float* C = (float*)Cv;
                size_t idx = (size_t)row * N + col;
                float2 v0 = {acc[m][n][0] * scale, acc[m][n][1] * scale};
                float2 v1 = {acc[m][n][2] * scale, acc[m][n][3] * scale};
                *(float2*)&C[idx] = v0;
                *(float2*)&C[idx + (size_t)8 * N] = v1;
            }
        }
    }
}

// Q/K/V projections in ONE launch: grid.z picks operands.
struct QKVArgs {
    const __half* A[3];
    const __half* B[3];
    __half* C[3];
    float scale[3];
};
__global__ __launch_bounds__(256) void gemm_qkv(QKVArgs a) {
    int z = blockIdx.z;
    gemm_body<true>(a.A[z], a.B[z], a.C[z], a.scale[z]);
}

__global__ __launch_bounds__(256) void gemm_out(const __half* __restrict__ A,
                                                const __half* __restrict__ B,
                                                float* __restrict__ C) {
    gemm_body<false>(A, B, C, 1.0f);
}

// ---------------------------------------------------------------------------
// Kernel 3: flash attention. CTA = (128 q rows, 1 head), 4 warps, each warp
// owns 32 q-rows (two 16-row mma groups). K/V fragments loaded ONCE per kk
// and reused for both row groups -> smem LDSM traffic per q-row halves vs
// the 8-warp/16-row layout (R14 post-mortem: smem-port bound).
// P in registers; l via ones-column MMA; masking by plain add (underflow).
// ---------------------------------------------------------------------------
#define KV_SZ (64 * 72)
#define ATTN_SMEM ((128 * 72 + 4 * KV_SZ) * 2)  // 55296 B

__global__ __launch_bounds__(128, 2) void attn_kernel() {
    extern __shared__ __half smh[];
    __half* Qs = smh;                  // [128][72]
    __half* Ksb = smh + 128 * 72;      // [2][64][72]
    __half* Vsb = Ksb + 2 * KV_SZ;     // [2][64][72]

    const int b = blockIdx.z, h = blockIdx.y, qt = blockIdx.x;
    const int tid = threadIdx.x, lane = tid & 31, wid = tid >> 5;
    const int g = lane >> 2, t4 = lane & 3;
    const int wrow = wid * 32;  // 4 warps x 32 rows
    const int arow = (lane & 7) + ((lane >> 3) & 1) * 8;  // A-style / trans-B
    const int acol = (lane >> 4) * 8;
    const int brow = (lane & 7) + (lane >> 4) * 8;        // non-trans B (S)
    const int bcol = ((lane >> 3) & 1) * 8;
    // constant B fragment: ones in column n=0 -> row-sum of P via the MMA
    const unsigned bb = (g == 0) ? 0x3C003C00u : 0u;

    const __half* Qp = g_Qh + ((size_t)(b * NH + h) * LL + qt * TQ) * DKV;
    const __half* Kp = g_Kh + (size_t)(b * NH + h) * LL * DKV;
    const __half* Vp = g_Vh + (size_t)(b * NH + h) * LL * DKV;
    const __half* BMp = g_BMh + ((size_t)b * LL + qt * TQ) * LL;

    auto issue_kv = [&](int kt, int buf) {
#pragma unroll
        for (int i = 0; i < 4; i++) {
            int f = tid + i * 128, r = f >> 3, c8 = (f & 7) * 8;
            cpa16(Ksb + buf * KV_SZ + r * 72 + c8,
                  Kp + (size_t)(kt * TK + r) * 64 + c8);
            cpa16(Vsb + buf * KV_SZ + r * 72 + c8,
                  Vp + (size_t)(kt * TK + r) * 64 + c8);
        }
    };

    // Q tile (once) + first K/V tile, one cp.async group
#pragma unroll
    for (int i = 0; i < 8; i++) {
        int f = tid + i * 128, r = f >> 3, c8 = (f & 7) * 8;
        cpa16(Qs + r * 72 + c8, Qp + (size_t)r * 64 + c8);
    }
    issue_kv(0, 0);
    CPCOMMIT;

    float m_i[2][2] = {{-1e30f, -1e30f}, {-1e30f, -1e30f}};
    float lacc[2][4] = {{0.f, 0.f, 0.f, 0.f}, {0.f, 0.f, 0.f, 0.f}};
    float oacc[2][8][4];
#pragma unroll
    for (int mg = 0; mg < 2; mg++)
#pragma unroll
        for (int nf = 0; nf < 8; nf++)
#pragma unroll
            for (int i = 0; i < 4; i++) oacc[mg][nf][i] = 0.f;

    for (int kt = 0; kt < NT; kt++) {
        int cur = kt & 1;
        CPWAIT(0);
        __syncthreads();
        if (kt + 1 < NT) {
            issue_kv(kt + 1, cur ^ 1);
            CPCOMMIT;
        }
        __half* Ks = Ksb + cur * KV_SZ;
        __half* Vs = Vsb + cur * KV_SZ;

        // S = Q @ K^T for BOTH 16-row groups; K fragments loaded once per kk
        float sacc[2][8][4];
#pragma unroll
        for (int mg = 0; mg < 2; mg++)
#pragma unroll
            for (int nf = 0; nf < 8; nf++)
#pragma unroll
                for (int i = 0; i < 4; i++) sacc[mg][nf][i] = 0.f;
#pragma unroll
        for (int kk = 0; kk < 4; kk++) {
            unsigned aq[2][4];
#pragma unroll
            for (int mg = 0; mg < 2; mg++)
                ldsm4(aq[mg][0], aq[mg][1], aq[mg][2], aq[mg][3],
                      s2u(Qs + (wrow + mg * 16 + arow) * 72 + kk * 16 + acol));
#pragma unroll
            for (int np = 0; np < 4; np++) {
                unsigned r0, r1, r2, r3;
                ldsm4(r0, r1, r2, r3,
                      s2u(Ks + (np * 16 + brow) * 72 + kk * 16 + bcol));
#pragma unroll
                for (int mg = 0; mg < 2; mg++) {
                    mma16(sacc[mg][np * 2], aq[mg][0], aq[mg][1], aq[mg][2],
                          aq[mg][3], r0, r1);
                    mma16(sacc[mg][np * 2 + 1], aq[mg][0], aq[mg][1],
                          aq[mg][2], aq[mg][3], r2, r3);
                }
            }
        }

        // Per row group: bias add (masked -> underflow), softmax, pack P
        unsigned pk[2][16];
        float alpha[2][2];
#pragma unroll
        for (int mg = 0; mg < 2; mg++) {
            const int rbase = wrow + mg * 16;
            float mloc[2] = {-1e30f, -1e30f};
            __half2 bm[8];
#pragma unroll
            for (int nf = 0; nf < 4; nf++)
#pragma unroll
                for (int rr = 0; rr < 2; rr++)
                    bm[nf * 2 + rr] = *(const __half2*)(
                        BMp + (size_t)(rbase + g + rr * 8) * LL + kt * TK +
                        nf * 8 + 2 * t4);
#pragma unroll
            for (int nf = 0; nf < 4; nf++) {
#pragma unroll
                for (int rr = 0; rr < 2; rr++) {
                    float2 bv = __half22float2(bm[nf * 2 + rr]);
                    float s0 = sacc[mg][nf][rr * 2 + 0] + bv.x;
                    float s1 = sacc[mg][nf][rr * 2 + 1] + bv.y;
                    sacc[mg][nf][rr * 2 + 0] = s0;
                    sacc[mg][nf][rr * 2 + 1] = s1;
                    mloc[rr] = fmaxf(mloc[rr], fmaxf(s0, s1));
                }
            }
#pragma unroll
            for (int nf = 0; nf < 4; nf++)
#pragma unroll
                for (int rr = 0; rr < 2; rr++)
                    bm[nf * 2 + rr] = *(const __half2*)(
                        BMp + (size_t)(rbase + g + rr * 8) * LL + kt * TK +
                        (nf + 4) * 8 + 2 * t4);
#pragma unroll
            for (int nf = 4; nf < 8; nf++) {
#pragma unroll
                for (int rr = 0; rr < 2; rr++) {
                    float2 bv = __half22float2(bm[(nf - 4) * 2 + rr]);
                    float s0 = sacc[mg][nf][rr * 2 + 0] + bv.x;
                    float s1 = sacc[mg][nf][rr * 2 + 1] + bv.y;
                    sacc[mg][nf][rr * 2 + 0] = s0;
                    sacc[mg][nf][rr * 2 + 1] = s1;
                    mloc[rr] = fmaxf(mloc[rr], fmaxf(s0, s1));
                }
            }
#pragma unroll
            for (int rr = 0; rr < 2; rr++) {
                mloc[rr] =
                    fmaxf(mloc[rr], __shfl_xor_sync(0xffffffffu, mloc[rr], 1));
                mloc[rr] =
                    fmaxf(mloc[rr], __shfl_xor_sync(0xffffffffu, mloc[rr], 2));
            }
            float nmL[2];
#pragma unroll
            for (int rr = 0; rr < 2; rr++) {
                float mn = fmaxf(m_i[mg][rr], mloc[rr]);
                alpha[mg][rr] = ex2f((m_i[mg][rr] - mn) * L2E);
                m_i[mg][rr] = mn;
                nmL[rr] = -mn * L2E;
            }
#pragma unroll
            for (int nf = 0; nf < 8; nf++) {
#pragma unroll
                for (int rr = 0; rr < 2; rr++) {
                    float p0 =
                        ex2f(fmaf(sacc[mg][nf][rr * 2 + 0], L2E, nmL[rr]));
                    float p1 =
                        ex2f(fmaf(sacc[mg][nf][rr * 2 + 1], L2E, nmL[rr]));
                    pk[mg][nf * 2 + rr] = pack2(p0, p1);
                }
            }
            // rescale running O and l by alpha
#pragma unroll
            for (int nf = 0; nf < 8; nf++) {
                oacc[mg][nf][0] *= alpha[mg][0];
                oacc[mg][nf][1] *= alpha[mg][0];
                oacc[mg][nf][2] *= alpha[mg][1];
                oacc[mg][nf][3] *= alpha[mg][1];
            }
            lacc[mg][0] *= alpha[mg][0];
            lacc[mg][1] *= alpha[mg][0];
            lacc[mg][2] *= alpha[mg][1];
            lacc[mg][3] *= alpha[mg][1];
        }

        // O += P @ V ; l += P @ ones. V fragments loaded once, reused per mg.
#pragma unroll
        for (int kk = 0; kk < 4; kk++) {
#pragma unroll
            for (int mg = 0; mg < 2; mg++)
                mma16(lacc[mg], pk[mg][4 * kk + 0], pk[mg][4 * kk + 1],
                      pk[mg][4 * kk + 2], pk[mg][4 * kk + 3], bb, bb);
#pragma unroll
            for (int np = 0; np < 4; np++) {
                unsigned r0, r1, r2, r3;
                ldsm4t(r0, r1, r2, r3,
                       s2u(Vs + (kk * 16 + arow) * 72 + np * 16 + acol));
#pragma unroll
                for (int mg = 0; mg < 2; mg++) {
                    mma16(oacc[mg][np * 2], pk[mg][4 * kk + 0],
                          pk[mg][4 * kk + 1], pk[mg][4 * kk + 2],
                          pk[mg][4 * kk + 3], r0, r1);
                    mma16(oacc[mg][np * 2 + 1], pk[mg][4 * kk + 0],
                          pk[mg][4 * kk + 1], pk[mg][4 * kk + 2],
                          pk[mg][4 * kk + 3], r2, r3);
                }
            }
        }
    }

    // l lives in column 0 of each lacc fragment; broadcast within each quad.
#pragma unroll
    for (int mg = 0; mg < 2; mg++) {
        float l0 = __shfl_sync(0xffffffffu, lacc[mg][0], lane & ~3);
        float l1 = __shfl_sync(0xffffffffu, lacc[mg][2], lane & ~3);
        float inv0 = 1.f / l0, inv1 = 1.f / l1;
#pragma unroll
        for (int nf = 0; nf < 8; nf++) {
            int col = nf * 8 + 2 * t4;
            int row = qt * TQ + wrow + mg * 16 + g;
            size_t idx = ((size_t)b * LL + row) * DM + h * DKV + col;
            *(__half2*)&g_O[idx] = __floats2half2_rn(oacc[mg][nf][0] * inv0,
                                                     oacc[mg][nf][1] * inv0);
            *(__half2*)&g_O[idx + (size_t)8 * DM] = __floats2half2_rn(
                oacc[mg][nf][2] * inv1, oacc[mg][nf][3] * inv1);
        }
    }
}

// ---------------------------------------------------------------------------
// Launch
// ---------------------------------------------------------------------------
extern "C" void kernel_launch(void* const* d_in, const int* in_sizes, int n_in,
                              void* d_out, int out_size) {
    float* out = (float*)d_out;

    __half *hq, *hk, *hv, *hw, *Qh, *Kh, *Vh, *O, *BMh;
    cudaGetSymbolAddress((void**)&hq, g_hq);
    cudaGetSymbolAddress((void**)&hk, g_hk);
    cudaGetSymbolAddress((void**)&hv, g_hv);
    cudaGetSymbolAddress((void**)&hw, g_hw);
    cudaGetSymbolAddress((void**)&Qh, g_Qh);
    cudaGetSymbolAddress((void**)&Kh, g_Kh);
    cudaGetSymbolAddress((void**)&Vh, g_Vh);
    cudaGetSymbolAddress((void**)&BMh, g_BMh);
    cudaGetSymbolAddress((void**)&O, g_O);
    size_t WSZ = (size_t)DM * DM;

    cudaFuncSetAttribute(attn_kernel,
                         cudaFuncAttributeMaxDynamicSharedMemorySize,
                         ATTN_SMEM);
    cudaFuncSetAttribute(gemm_qkv,
                         cudaFuncAttributeMaxDynamicSharedMemorySize,
                         GEMM_SMEM);
    cudaFuncSetAttribute(gemm_out,
                         cudaFuncAttributeMaxDynamicSharedMemorySize,
                         GEMM_SMEM);

    // 0. merged prep: fp32->fp16 converts + mask/bias fusion (BM as fp16)
    PrepArgs pa;
    pa.s[0] = (const float4*)d_in[0];
    pa.s[1] = (const float4*)d_in[1];
    pa.s[2] = (const float4*)d_in[2];
    pa.s[3] = (const float4*)d_in[5];
    pa.s[4] = (const float4*)d_in[6];
    pa.s[5] = (const float4*)d_in[7];
    pa.s[6] = (const float4*)d_in[8];
    pa.d[0] = (uint2*)hq;
    pa.d[1] = (uint2*)hk;
    pa.d[2] = (uint2*)hv;
    pa.d[3] = (uint2*)(hw + 0 * WSZ);
    pa.d[4] = (uint2*)(hw + 1 * WSZ);
    pa.d[5] = (uint2*)(hw + 2 * WSZ);
    pa.d[6] = (uint2*)(hw + 3 * WSZ);
    pa.mask = (const int4*)d_in[3];
    pa.bias = (const float4*)d_in[4];
    pa.bmh = (uint2*)BMh;
    prep_kernel<<<4096 + 8192, 256>>>(pa);

    // 1. Q/K/V projections in one launch (Q pre-scaled by 1/8)
    QKVArgs qa;
    qa.A[0] = hq;
    qa.A[1] = hk;
    qa.A[2] = hv;
    qa.B[0] = hw + 0 * WSZ;
    qa.B[1] = hw + 1 * WSZ;
    qa.B[2] = hw + 2 * WSZ;
    qa.C[0] = Qh;
    qa.C[1] = Kh;
    qa.C[2] = Vh;
    qa.scale[0] = 0.125f;
    qa.scale[1] = 1.0f;
    qa.scale[2] = 1.0f;
    gemm_qkv<<<dim3(DM / 128, (BB * LL) / 128, 3), 256, GEMM_SMEM>>>(qa);

    // 2. attention (128 threads, 4 warps x 32 q-rows)
    attn_kernel<<<dim3(LL / TQ, NH, BB), 128, ATTN_SMEM>>>();

    // 3. output projection (half in, fp32 out)
    gemm_out<<<dim3(DM / 128, (BB * LL) / 128), 256, GEMM_SMEM>>>(
        O, hw + 3 * WSZ, out);
}

// round 16
// speedup vs baseline: 1.7773x; 1.0331x over previous
#include <cuda_runtime.h>
#include <cuda_fp16.h>

#define BB 2
#define LL 2048
#define DM 1024
#define NH 16
#define DKV 64
#define NEGV (-10000.0f)
#define TQA 64
#define TK 64
#define NT (LL / TK)
#define L2E 1.4426950408889634f

// Scratch (device globals: allocation-free per harness rules)
__device__ __align__(16) __half g_hq[(size_t)BB * LL * DM];
__device__ __align__(16) __half g_hk[(size_t)BB * LL * DM];
__device__ __align__(16) __half g_hv[(size_t)BB * LL * DM];
__device__ __align__(16) __half g_hw[4][(size_t)DM * DM];
__device__ __align__(16) __half g_Qh[(size_t)BB * NH * LL * DKV];
__device__ __align__(16) __half g_Kh[(size_t)BB * NH * LL * DKV];
__device__ __align__(16) __half g_Vh[(size_t)BB * NH * LL * DKV];
__device__ __align__(16) __half g_BMh[(size_t)BB * LL * LL];
__device__ __align__(16) __half g_O[(size_t)BB * LL * DM];

__device__ __forceinline__ unsigned pack2(float x, float y) {
    __half2 h = __floats2half2_rn(x, y);
    return *reinterpret_cast<unsigned*>(&h);
}

__device__ __forceinline__ float ex2f(float x) {
    float y;
    asm("ex2.approx.f32 %0,%1;" : "=f"(y) : "f"(x));
    return y;
}

__device__ __forceinline__ unsigned s2u(const void* p) {
    return (unsigned)__cvta_generic_to_shared(p);
}

__device__ __forceinline__ void cpa16(void* dst, const void* src) {
    asm volatile("cp.async.cg.shared.global [%0],[%1],16;" ::"r"(s2u(dst)),
                 "l"(src));
}
#define CPCOMMIT asm volatile("cp.async.commit_group;")
#define CPWAIT(n) asm volatile("cp.async.wait_group %0;" ::"n"(n))

__device__ __forceinline__ void ldsm4(unsigned& r0, unsigned& r1, unsigned& r2,
                                      unsigned& r3, unsigned addr) {
    asm volatile("ldmatrix.sync.aligned.m8n8.x4.shared.b16 {%0,%1,%2,%3},[%4];"
                 : "=r"(r0), "=r"(r1), "=r"(r2), "=r"(r3)
                 : "r"(addr));
}

__device__ __forceinline__ void ldsm4t(unsigned& r0, unsigned& r1, unsigned& r2,
                                       unsigned& r3, unsigned addr) {
    asm volatile(
        "ldmatrix.sync.aligned.m8n8.x4.trans.shared.b16 {%0,%1,%2,%3},[%4];"
        : "=r"(r0), "=r"(r1), "=r"(r2), "=r"(r3)
        : "r"(addr));
}

__device__ __forceinline__ void mma16(float* c, unsigned a0, unsigned a1,
                                      unsigned a2, unsigned a3, unsigned b0,
                                      unsigned b1) {
    asm volatile(
        "mma.sync.aligned.m16n8k16.row.col.f32.f16.f16.f32 "
        "{%0,%1,%2,%3},{%4,%5,%6,%7},{%8,%9},{%0,%1,%2,%3};"
        : "+f"(c[0]), "+f"(c[1]), "+f"(c[2]), "+f"(c[3])
        : "r"(a0), "r"(a1), "r"(a2), "r"(a3), "r"(b0), "r"(b1));
}

// ---------------------------------------------------------------------------
// Kernel 0: merged prep. Blocks [0,4096): fp32->fp16 convert of activations
// + weights. Blocks [4096,12288): fuse mask+bias -> BM (fp16; -10000 is
// exactly representable in half so masking semantics are preserved).
// ---------------------------------------------------------------------------
struct PrepArgs {
    const float4* s[7];
    uint2* d[7];
    const int4* mask;
    const float4* bias;
    uint2* bmh;
};
__global__ __launch_bounds__(256) void prep_kernel(PrepArgs a) {
    int bid = blockIdx.x;
    if (bid < 4096) {
        int ti, base;
        if (bid < 3072) {
            ti = bid >> 10;
            base = bid & 1023;
        } else {
            ti = 3 + ((bid - 3072) >> 8);
            base = (bid - 3072) & 255;
        }
        const float4* s = a.s[ti];
        uint2* d = a.d[ti];
        size_t off = (size_t)base * 1024 + threadIdx.x;
#pragma unroll
        for (int i = 0; i < 4; i++) {
            float4 v = s[off + i * 256];
            uint2 u;
            u.x = pack2(v.x, v.y);
            u.y = pack2(v.z, v.w);
            d[off + i * 256] = u;
        }
    } else {
        size_t i = (size_t)(bid - 4096) * 256 + threadIdx.x;
        int4 m = a.mask[i];
        float4 bv = a.bias[i];
        uint2 r;
        r.x = pack2(m.x ? bv.x : NEGV, m.y ? bv.y : NEGV);
        r.y = pack2(m.z ? bv.z : NEGV, m.w ? bv.w : NEGV);
        a.bmh[i] = r;
    }
}

// ---------------------------------------------------------------------------
// GEMM body: pure-fp16, C = A@B * scale, fp32 accumulate. M=4096 N=K=1024.
// 128x128x32 tiles, 8 warps (2x4), m16n8k16 + ldmatrix, 3-stage cp.async.
// Plain launch_bounds(256): 94 regs, NO spill.
// HSPLIT: C is __half head-split layout [b][h][l][64]; else fp32 row-major.
// ---------------------------------------------------------------------------
#define GA_ST 40
#define GB_ST 136
#define GA_SZ (128 * GA_ST)
#define GB_SZ (32 * GB_ST)
#define GEMM_SMEM ((3 * GA_SZ + 3 * GB_SZ) * 2)

template <bool HSPLIT>
__device__ __forceinline__ void gemm_body(const __half* __restrict__ A,
                                          const __half* __restrict__ B,
                                          void* __restrict__ Cv, float scale) {
    extern __shared__ __half gsm[];
    const int K = DM, N = DM;
    const int tid = threadIdx.x, lane = tid & 31, wid = tid >> 5;
    const int g = lane >> 2, t4 = lane & 3;
    const int wm = wid >> 2, wn = wid & 3;
    const int row0 = blockIdx.y * 128, col0 = blockIdx.x * 128;
    const int arow = (lane & 7) + ((lane >> 3) & 1) * 8;
    const int acol = (lane >> 4) * 8;

    float acc[4][4][4];
#pragma unroll
    for (int m = 0; m < 4; m++)
#pragma unroll
        for (int n = 0; n < 4; n++)
#pragma unroll
            for (int i = 0; i < 4; i++) acc[m][n][i] = 0.f;

    auto issue = [&](int kt) {
        int buf = kt % 3;
        __half* As = gsm + buf * GA_SZ;
        __half* Bs = gsm + 3 * GA_SZ + buf * GB_SZ;
#pragma unroll
        for (int i = 0; i < 2; i++) {
            int f = tid + i * 256, r = f >> 2, c8 = (f & 3) * 8;
            cpa16(As + r * GA_ST + c8,
                  A + (size_t)(row0 + r) * K + kt * 32 + c8);
        }
#pragma unroll
        for (int i = 0; i < 2; i++) {
            int f = tid + i * 256, r = f >> 4, c8 = (f & 15) * 8;
            cpa16(Bs + r * GB_ST + c8,
                  B + (size_t)(kt * 32 + r) * N + col0 + c8);
        }
    };

    const int nk = K / 32;
    issue(0);
    CPCOMMIT;
    issue(1);
    CPCOMMIT;

    for (int kt = 0; kt < nk; kt++) {
        CPWAIT(1);
        __syncthreads();
        int buf = kt % 3;
        __half* As = gsm + buf * GA_SZ;
        __half* Bs = gsm + 3 * GA_SZ + buf * GB_SZ;
#pragma unroll
        for (int kk = 0; kk < 2; kk++) {
            unsigned af[4][4];
#pragma unroll
            for (int m = 0; m < 4; m++)
                ldsm4(af[m][0], af[m][1], af[m][2], af[m][3],
                      s2u(As + (wm * 64 + m * 16 + arow) * GA_ST + kk * 16 +
                          acol));
            unsigned bf[4][2];
#pragma unroll
            for (int np = 0; np < 2; np++) {
                unsigned r0, r1, r2, r3;
                ldsm4t(r0, r1, r2, r3,
                       s2u(Bs + (kk * 16 + arow) * GB_ST + wn * 32 + np * 16 +
                           acol));
                bf[np * 2][0] = r0;
                bf[np * 2][1] = r1;
                bf[np * 2 + 1][0] = r2;
                bf[np * 2 + 1][1] = r3;
            }
#pragma unroll
            for (int m = 0; m < 4; m++)
#pragma unroll
                for (int n = 0; n < 4; n++)
                    mma16(acc[m][n], af[m][0], af[m][1], af[m][2], af[m][3],
                          bf[n][0], bf[n][1]);
        }
        if (kt + 2 < nk) issue(kt + 2);
        CPCOMMIT;
    }

#pragma unroll
    for (int m = 0; m < 4; m++) {
#pragma unroll
        for (int n = 0; n < 4; n++) {
            int row = row0 + wm * 64 + m * 16 + g;
            int col = col0 + wn * 32 + n * 8 + 2 * t4;
            if (HSPLIT) {
                __half* C = (__half*)Cv;
                int b = row >> 11, l = row & (LL - 1);
                int h = col >> 6, d = col & 63;
                size_t idx = ((size_t)(b * NH + h) * LL + l) * 64 + d;
                *(__half2*)&C[idx] = __floats2half2_rn(acc[m][n][0] * scale,
                                                       acc[m][n][1] * scale);
                *(__half2*)&C[idx + (size_t)8 * 64] = __floats2half2_rn(
                    acc[m][n][2] * scale, acc[m][n][3] * scale);
            } else {
                float* C = (float*)Cv;
                size_t idx = (size_t)row * N + col;
                float2 v0 = {acc[m][n][0] * scale, acc[m][n][1] * scale};
                float2 v1 = {acc[m][n][2] * scale, acc[m][n][3] * scale};
                *(float2*)&C[idx] = v0;
                *(float2*)&C[idx + (size_t)8 * N] = v1;
            }
        }
    }
}

// Q/K/V projections in ONE launch: grid.z picks operands.
struct QKVArgs {
    const __half* A[3];
    const __half* B[3];
    __half* C[3];
    float scale[3];
};
__global__ __launch_bounds__(256) void gemm_qkv(QKVArgs a) {
    int z = blockIdx.z;
    gemm_body<true>(a.A[z], a.B[z], a.C[z], a.scale[z]);
}

__global__ __launch_bounds__(256) void gemm_out(const __half* __restrict__ A,
                                                const __half* __restrict__ B,
                                                float* __restrict__ C) {
    gemm_body<false>(A, B, C, 1.0f);
}

// ---------------------------------------------------------------------------
// Kernel 3: flash attention. CTA = (64 q rows, 1 head), 4 warps x 16 rows,
// 4 CTAs/SM (16 warps/SM = 4/SMSP) for latency hiding — R15 post-mortem:
// attention is latency-bound (smem/L2/tensor/MUFU floors all ~4x below
// measured), so this doubles the warps available to hide the serial
// softmax chain. Per-warp code identical to R11's proven path.
// P in registers; l via ones-column MMA; masking by plain add (underflow).
// ---------------------------------------------------------------------------
#define KV_SZ (64 * 72)
#define ATTN_SMEM ((64 * 72 + 4 * KV_SZ) * 2)  // 46080 B -> 4 CTAs/SM

__global__ __launch_bounds__(128, 4) void attn_kernel() {
    extern __shared__ __half smh[];
    __half* Qs = smh;                 // [64][72]
    __half* Ksb = smh + 64 * 72;      // [2][64][72]
    __half* Vsb = Ksb + 2 * KV_SZ;    // [2][64][72]

    const int b = blockIdx.z, h = blockIdx.y, qt = blockIdx.x;
    const int tid = threadIdx.x, lane = tid & 31, wid = tid >> 5;
    const int g = lane >> 2, t4 = lane & 3;
    const int wrow = wid * 16;  // 4 warps x 16 rows
    const int arow = (lane & 7) + ((lane >> 3) & 1) * 8;  // A-style / trans-B
    const int acol = (lane >> 4) * 8;
    const int brow = (lane & 7) + (lane >> 4) * 8;        // non-trans B (S)
    const int bcol = ((lane >> 3) & 1) * 8;
    // constant B fragment: ones in column n=0 -> row-sum of P via the MMA
    const unsigned bb = (g == 0) ? 0x3C003C00u : 0u;

    const __half* Qp = g_Qh + ((size_t)(b * NH + h) * LL + qt * TQA) * DKV;
    const __half* Kp = g_Kh + (size_t)(b * NH + h) * LL * DKV;
    const __half* Vp = g_Vh + (size_t)(b * NH + h) * LL * DKV;
    const __half* BMp = g_BMh + ((size_t)b * LL + qt * TQA) * LL;

    auto issue_kv = [&](int kt, int buf) {
#pragma unroll
        for (int i = 0; i < 4; i++) {
            int f = tid + i * 128, r = f >> 3, c8 = (f & 7) * 8;
            cpa16(Ksb + buf * KV_SZ + r * 72 + c8,
                  Kp + (size_t)(kt * TK + r) * 64 + c8);
            cpa16(Vsb + buf * KV_SZ + r * 72 + c8,
                  Vp + (size_t)(kt * TK + r) * 64 + c8);
        }
    };

    // Q tile (once) + first K/V tile, one cp.async group
#pragma unroll
    for (int i = 0; i < 4; i++) {
        int f = tid + i * 128, r = f >> 3, c8 = (f & 7) * 8;
        cpa16(Qs + r * 72 + c8, Qp + (size_t)r * 64 + c8);
    }
    issue_kv(0, 0);
    CPCOMMIT;

    float m_i[2] = {-1e30f, -1e30f};
    float lacc[4] = {0.f, 0.f, 0.f, 0.f};
    float oacc[8][4];
#pragma unroll
    for (int nf = 0; nf < 8; nf++)
#pragma unroll
        for (int i = 0; i < 4; i++) oacc[nf][i] = 0.f;

    for (int kt = 0; kt < NT; kt++) {
        int cur = kt & 1;
        CPWAIT(0);
        __syncthreads();
        if (kt + 1 < NT) {
            issue_kv(kt + 1, cur ^ 1);
            CPCOMMIT;
        }
        __half* Ks = Ksb + cur * KV_SZ;
        __half* Vs = Vsb + cur * KV_SZ;

        // BM batch 0 (nf 0..3): fp16 gmem -> regs, hidden under the S-mma
        __half2 bm[8];
#pragma unroll
        for (int nf = 0; nf < 4; nf++)
#pragma unroll
            for (int rr = 0; rr < 2; rr++)
                bm[nf * 2 + rr] = *(const __half2*)(
                    BMp + (size_t)(wrow + g + rr * 8) * LL + kt * TK + nf * 8 +
                    2 * t4);

        // S = Q @ K^T
        float sacc[8][4];
#pragma unroll
        for (int nf = 0; nf < 8; nf++)
#pragma unroll
            for (int i = 0; i < 4; i++) sacc[nf][i] = 0.f;
#pragma unroll
        for (int kk = 0; kk < 4; kk++) {
            unsigned a0, a1, a2, a3;
            ldsm4(a0, a1, a2, a3,
                  s2u(Qs + (wrow + arow) * 72 + kk * 16 + acol));
#pragma unroll
            for (int np = 0; np < 4; np++) {
                unsigned r0, r1, r2, r3;
                ldsm4(r0, r1, r2, r3,
                      s2u(Ks + (np * 16 + brow) * 72 + kk * 16 + bcol));
                mma16(sacc[np * 2], a0, a1, a2, a3, r0, r1);
                mma16(sacc[np * 2 + 1], a0, a1, a2, a3, r2, r3);
            }
        }

        // bias/mask: plain add (masked -> s-10000 -> exp underflows to 0,
        // matching the reference's replace-then-softmax exactly)
        float mloc[2] = {-1e30f, -1e30f};
#pragma unroll
        for (int nf = 0; nf < 4; nf++) {
#pragma unroll
            for (int rr = 0; rr < 2; rr++) {
                float2 bv = __half22float2(bm[nf * 2 + rr]);
                float s0 = sacc[nf][rr * 2 + 0] + bv.x;
                float s1 = sacc[nf][rr * 2 + 1] + bv.y;
                sacc[nf][rr * 2 + 0] = s0;
                sacc[nf][rr * 2 + 1] = s1;
                mloc[rr] = fmaxf(mloc[rr], fmaxf(s0, s1));
            }
        }
        // BM batch 1 (nf 4..7) reuses the same registers
#pragma unroll
        for (int nf = 0; nf < 4; nf++)
#pragma unroll
            for (int rr = 0; rr < 2; rr++)
                bm[nf * 2 + rr] = *(const __half2*)(
                    BMp + (size_t)(wrow + g + rr * 8) * LL + kt * TK +
                    (nf + 4) * 8 + 2 * t4);
#pragma unroll
        for (int nf = 4; nf < 8; nf++) {
#pragma unroll
            for (int rr = 0; rr < 2; rr++) {
                float2 bv = __half22float2(bm[(nf - 4) * 2 + rr]);
                float s0 = sacc[nf][rr * 2 + 0] + bv.x;
                float s1 = sacc[nf][rr * 2 + 1] + bv.y;
                sacc[nf][rr * 2 + 0] = s0;
                sacc[nf][rr * 2 + 1] = s1;
                mloc[rr] = fmaxf(mloc[rr], fmaxf(s0, s1));
            }
        }
#pragma unroll
        for (int rr = 0; rr < 2; rr++) {
            mloc[rr] = fmaxf(mloc[rr], __shfl_xor_sync(0xffffffffu, mloc[rr], 1));
            mloc[rr] = fmaxf(mloc[rr], __shfl_xor_sync(0xffffffffu, mloc[rr], 2));
        }
        float alpha[2], nmL[2];
#pragma unroll
        for (int rr = 0; rr < 2; rr++) {
            float mn = fmaxf(m_i[rr], mloc[rr]);
            alpha[rr] = ex2f((m_i[rr] - mn) * L2E);
            m_i[rr] = mn;
            nmL[rr] = -mn * L2E;
        }
        // P = exp2(s*log2e - m*log2e), packed straight to half2 A-fragments
        unsigned pk[16];
#pragma unroll
        for (int nf = 0; nf < 8; nf++) {
#pragma unroll
            for (int rr = 0; rr < 2; rr++) {
                float p0 = ex2f(fmaf(sacc[nf][rr * 2 + 0], L2E, nmL[rr]));
                float p1 = ex2f(fmaf(sacc[nf][rr * 2 + 1], L2E, nmL[rr]));
                pk[nf * 2 + rr] = pack2(p0, p1);
            }
        }
        // rescale running O and l by alpha
#pragma unroll
        for (int nf = 0; nf < 8; nf++) {
            oacc[nf][0] *= alpha[0];
            oacc[nf][1] *= alpha[0];
            oacc[nf][2] *= alpha[1];
            oacc[nf][3] *= alpha[1];
        }
        lacc[0] *= alpha[0];
        lacc[1] *= alpha[0];
        lacc[2] *= alpha[1];
        lacc[3] *= alpha[1];

        // O += P @ V ; l += P @ ones (constant B fragment, col 0)
#pragma unroll
        for (int kk = 0; kk < 4; kk++) {
            unsigned a0 = pk[4 * kk + 0], a1 = pk[4 * kk + 1];
            unsigned a2 = pk[4 * kk + 2], a3 = pk[4 * kk + 3];
            mma16(lacc, a0, a1, a2, a3, bb, bb);
#pragma unroll
            for (int np = 0; np < 4; np++) {
                unsigned r0, r1, r2, r3;
                ldsm4t(r0, r1, r2, r3,
                       s2u(Vs + (kk * 16 + arow) * 72 + np * 16 + acol));
                mma16(oacc[np * 2], a0, a1, a2, a3, r0, r1);
                mma16(oacc[np * 2 + 1], a0, a1, a2, a3, r2, r3);
            }
        }
    }

    // l lives in column 0 of the lacc fragment; broadcast within each quad.
    float l0 = __shfl_sync(0xffffffffu, lacc[0], lane & ~3);
    float l1 = __shfl_sync(0xffffffffu, lacc[2], lane & ~3);
    float inv0 = 1.f / l0, inv1 = 1.f / l1;
#pragma unroll
    for (int nf = 0; nf < 8; nf++) {
        int col = nf * 8 + 2 * t4;
        int row = qt * TQA + wrow + g;
        size_t idx = ((size_t)b * LL + row) * DM + h * DKV + col;
        *(__half2*)&g_O[idx] =
            __floats2half2_rn(oacc[nf][0] * inv0, oacc[nf][1] * inv0);
        *(__half2*)&g_O[idx + (size_t)8 * DM] =
            __floats2half2_rn(oacc[nf][2] * inv1, oacc[nf][3] * inv1);
    }
}

// ---------------------------------------------------------------------------
// Launch
// ---------------------------------------------------------------------------
extern "C" void kernel_launch(void* const* d_in, const int* in_sizes, int n_in,
                              void* d_out, int out_size) {
    float* out = (float*)d_out;

    __half *hq, *hk, *hv, *hw, *Qh, *Kh, *Vh, *O, *BMh;
    cudaGetSymbolAddress((void**)&hq, g_hq);
    cudaGetSymbolAddress((void**)&hk, g_hk);
    cudaGetSymbolAddress((void**)&hv, g_hv);
    cudaGetSymbolAddress((void**)&hw, g_hw);
    cudaGetSymbolAddress((void**)&Qh, g_Qh);
    cudaGetSymbolAddress((void**)&Kh, g_Kh);
    cudaGetSymbolAddress((void**)&Vh, g_Vh);
    cudaGetSymbolAddress((void**)&BMh, g_BMh);
    cudaGetSymbolAddress((void**)&O, g_O);
    size_t WSZ = (size_t)DM * DM;

    cudaFuncSetAttribute(attn_kernel,
                         cudaFuncAttributeMaxDynamicSharedMemorySize,
                         ATTN_SMEM);
    cudaFuncSetAttribute(gemm_qkv,
                         cudaFuncAttributeMaxDynamicSharedMemorySize,
                         GEMM_SMEM);
    cudaFuncSetAttribute(gemm_out,
                         cudaFuncAttributeMaxDynamicSharedMemorySize,
                         GEMM_SMEM);

    // 0. merged prep: fp32->fp16 converts + mask/bias fusion (BM as fp16)
    PrepArgs pa;
    pa.s[0] = (const float4*)d_in[0];
    pa.s[1] = (const float4*)d_in[1];
    pa.s[2] = (const float4*)d_in[2];
    pa.s[3] = (const float4*)d_in[5];
    pa.s[4] = (const float4*)d_in[6];
    pa.s[5] = (const float4*)d_in[7];
    pa.s[6] = (const float4*)d_in[8];
    pa.d[0] = (uint2*)hq;
    pa.d[1] = (uint2*)hk;
    pa.d[2] = (uint2*)hv;
    pa.d[3] = (uint2*)(hw + 0 * WSZ);
    pa.d[4] = (uint2*)(hw + 1 * WSZ);
    pa.d[5] = (uint2*)(hw + 2 * WSZ);
    pa.d[6] = (uint2*)(hw + 3 * WSZ);
    pa.mask = (const int4*)d_in[3];
    pa.bias = (const float4*)d_in[4];
    pa.bmh = (uint2*)BMh;
    prep_kernel<<<4096 + 8192, 256>>>(pa);

    // 1. Q/K/V projections in one launch (Q pre-scaled by 1/8)
    QKVArgs qa;
    qa.A[0] = hq;
    qa.A[1] = hk;
    qa.A[2] = hv;
    qa.B[0] = hw + 0 * WSZ;
    qa.B[1] = hw + 1 * WSZ;
    qa.B[2] = hw + 2 * WSZ;
    qa.C[0] = Qh;
    qa.C[1] = Kh;
    qa.C[2] = Vh;
    qa.scale[0] = 0.125f;
    qa.scale[1] = 1.0f;
    qa.scale[2] = 1.0f;
    gemm_qkv<<<dim3(DM / 128, (BB * LL) / 128, 3), 256, GEMM_SMEM>>>(qa);

    // 2. attention (64 q-rows/CTA, 4 warps x 16 rows, 4 CTAs/SM)
    attn_kernel<<<dim3(LL / TQA, NH, BB), 128, ATTN_SMEM>>>();

    // 3. output projection (half in, fp32 out)
    gemm_out<<<dim3(DM / 128, (BB * LL) / 128), 256, GEMM_SMEM>>>(
        O, hw + 3 * WSZ, out);
}